// round 13
// baseline (speedup 1.0000x reference)
#include <cuda_runtime.h>
#include <cuda_fp16.h>
#include <cuda_bf16.h>

// ---------------- problem constants ----------------
constexpr int B  = 32;
constexpr int S  = 400;
constexpr int T  = 64;
constexpr int TS = T - 1;      // 63 steps
constexpr int H  = 512;
constexpr int E  = 256;
constexpr int V  = 50000;
constexpr int NOOV = 50;
constexpr int VEXT = V + NOOV; // 50050
constexpr int G4H = 4 * H;     // 2048
constexpr int NK  = E + 2 * H; // 1280 combined LSTM K
constexpr int VB  = (V + 127) / 128;   // 391 vocab GEMM blocks
constexpr int VP  = VB * 128;          // 50048 padded vocab
constexpr int KV  = 2 * H;     // 1024

constexpr int NSB   = 1600;            // score blocks
constexpr int NSCAT = 50;              // scatter blocks
constexpr int NEXTV = (B * V) / 256;   // 6250 ext blocks
constexpr int GSC   = NSB + NSCAT + NEXTV;  // 7900

// output layout: all_dists [B][63][VEXT], h [B*H], c [B*H], cov_loss [1]
constexpr long OD = 0;
constexpr long OH = (long)B * TS * VEXT;   // 100900800
constexpr long OC = OH + (long)B * H;
constexpr long OL = OC + (long)B * H;

// ---------------- device scratch ----------------
__device__ uint2 g_Wp[(size_t)(VP / 8) * 64 * 32]; // 102.5 MB W_out fragments
__device__ __half g_enc_projh[B * S * H];          // 13.1 MB fp16 enc_proj
__device__ __half g_Wg[G4H * NK];                  // 5.2 MB fp16 LSTM weights [j][k]
__device__ float g_expl[B * V];                    // exp(logits)
__device__ float g_attn[B * S];                    // exp(score)
__device__ float g_attn2[B * S];                   // softmaxed attention
__device__ float g_cov[B * S];
__device__ float g_covloss[B];
__device__ float g_decproj[B * H];                 // includes +b_att
__device__ float g_context[B * H];
__device__ float g_hbuf[2 * B * H];                // double-buffered h
__device__ float g_c[B * H];
__device__ __half g_hch[B * KV];                   // [h_new | ctx] fp16
__device__ float g_pgen[B];
__device__ float g_pgenacc[B];
__device__ float g_expsum[B];
__device__ float g_rowsum[B];
__device__ float g_Wdt[H * H];                     // W_dec transposed

// ---------------- math helpers ----------------
__device__ __forceinline__ float my_exp(float x) { return __expf(x); }
__device__ __forceinline__ float my_tanh(float x) {
    float ax = fabsf(x);
    float t  = __expf(-2.0f * ax);
    float r  = __fdividef(1.0f - t, 1.0f + t);
    return copysignf(r, x);
}
__device__ __forceinline__ float my_sigm(float x) {
    return __fdividef(1.0f, 1.0f + __expf(-x));
}
__device__ __forceinline__ void mma16816(float& d0, float& d1, float& d2, float& d3,
                                         unsigned a0, unsigned a1, unsigned a2, unsigned a3,
                                         unsigned b0, unsigned b1) {
    asm("mma.sync.aligned.m16n8k16.row.col.f32.f16.f16.f32 "
        "{%0,%1,%2,%3}, {%4,%5,%6,%7}, {%8,%9}, {%0,%1,%2,%3};"
        : "+f"(d0), "+f"(d1), "+f"(d2), "+f"(d3)
        : "r"(a0), "r"(a1), "r"(a2), "r"(a3), "r"(b0), "r"(b1));
}

// ---------------- per-call: zero the dists region ----------------
__global__ void k_zero(float* __restrict__ out) {
    long i = (long)blockIdx.x * 256 + threadIdx.x;
    if (i < OH / 4) ((float4*)out)[i] = make_float4(0.f, 0.f, 0.f, 0.f);
}

// ---------------- one-off: repack W_out into mma B-fragment layout --------
__global__ __launch_bounds__(256) void k_wpack(const float* __restrict__ W) {
    long wdx = (long)blockIdx.x * 256 + threadIdx.x;   // 4-byte word index
    if (wdx >= (long)VP * KV / 2) return;
    long chunk = wdx >> 6;
    int ww = (int)(wdx & 63);
    int lane = ww >> 1, word = ww & 1;
    int g = lane >> 2, tg = lane & 3;
    long v8 = chunk >> 6;
    int ks  = (int)(chunk & 63);
    long v = v8 * 8 + g;
    int k = ks * 16 + tg * 2 + word * 8;
    __half2 hv;
    if (v < V) {
        float2 f = *(const float2*)(W + v * KV + k);
        hv = __floats2half2_rn(f.x, f.y);
    } else {
        hv = __floats2half2_rn(0.f, 0.f);
    }
    ((unsigned*)g_Wp)[wdx] = *(unsigned*)&hv;
}

// ---------------- one-off: pack LSTM weights fp16 [j][1280] ----------------
__global__ __launch_bounds__(256) void k_gpack(const float* __restrict__ W_ih,
                                               const float* __restrict__ W_hh) {
    long idx = ((long)blockIdx.x * 256 + threadIdx.x) * 4;
    if (idx >= (long)G4H * NK) return;
    int j = (int)(idx / NK), k = (int)(idx % NK);
    const float* src = (k < 768) ? W_ih + (size_t)j * 768 + k
                                 : W_hh + (size_t)j * 512 + (k - 768);
    float4 f = *(const float4*)src;
    __half2* dst = (__half2*)(g_Wg + idx);
    dst[0] = __floats2half2_rn(f.x, f.y);
    dst[1] = __floats2half2_rn(f.z, f.w);
}

// ---------------- one-off: transpose W_dec ----------------
__global__ __launch_bounds__(256) void k_prep(const float* __restrict__ W_dec) {
    __shared__ float tile[32][33];
    int x = blockIdx.x * 32, y = blockIdx.y * 32;
    int tx = threadIdx.x & 31, ty0 = threadIdx.x >> 5;
    for (int i = ty0; i < 32; i += 8)
        tile[i][tx] = W_dec[(y + i) * H + x + tx];
    __syncthreads();
    for (int i = ty0; i < 32; i += 8)
        g_Wdt[(x + i) * H + y + tx] = tile[tx][i];
}

// ---------------- setup: state init + initial decproj (+b_att) ------------
__global__ __launch_bounds__(512) void k_setup(const float* __restrict__ hidden,
                                               const float* __restrict__ cell,
                                               const float* __restrict__ W_dec,
                                               const float* __restrict__ b_att) {
    int b = blockIdx.x, h = threadIdx.x;
    __shared__ float sh[H];
    float hv = hidden[b * H + h];
    g_hbuf[b * H + h] = hv;              // parity 0
    g_c[b * H + h] = cell[b * H + h];
    g_context[b * H + h] = 0.0f;
    sh[h] = hv;
    if (h < S) g_cov[b * S + h] = 0.0f;
    if (h == 0) { g_covloss[b] = 0.0f; g_pgenacc[b] = 0.0f; }
    if (h == 1) { g_expsum[b] = 0.0f;  g_rowsum[b] = 0.0f; }
    __syncthreads();
    float acc = 0.0f;
    #pragma unroll 8
    for (int k = 0; k < H; k++) acc += sh[k] * W_dec[k * H + h];
    g_decproj[b * H + h] = acc + b_att[h];
}

// ---------------- enc_proj = encoder_outputs @ W_enc (fp32, fp16 out) ------
__global__ __launch_bounds__(256) void k_encproj(const float* __restrict__ A,
                                                 const float* __restrict__ Bm) {
    __shared__ float As[16][68];
    __shared__ float Bs[16][68];
    const int N = H, K = H;
    int bm = blockIdx.y * 64, bn = blockIdx.x * 64;
    int tx = threadIdx.x & 15, ty = threadIdx.x >> 4;
    float acc[4][4] = {};
    for (int k0 = 0; k0 < K; k0 += 16) {
        #pragma unroll
        for (int i = 0; i < 4; i++) {
            int lin = threadIdx.x + i * 256;
            int r = lin >> 4, c = lin & 15;
            As[c][r] = A[(size_t)(bm + r) * K + k0 + c];
            int r2 = lin >> 6, c2 = lin & 63;
            Bs[r2][c2] = Bm[(size_t)(k0 + r2) * N + bn + c2];
        }
        __syncthreads();
        #pragma unroll
        for (int kk = 0; kk < 16; kk++) {
            float4 a4 = *(const float4*)&As[kk][ty * 4];
            float4 b4 = *(const float4*)&Bs[kk][tx * 4];
            float av[4] = {a4.x, a4.y, a4.z, a4.w};
            float bv[4] = {b4.x, b4.y, b4.z, b4.w};
            #pragma unroll
            for (int i = 0; i < 4; i++)
                #pragma unroll
                for (int j = 0; j < 4; j++) acc[i][j] += av[i] * bv[j];
        }
        __syncthreads();
    }
    #pragma unroll
    for (int i = 0; i < 4; i++) {
        __half2 h0 = __floats2half2_rn(acc[i][0], acc[i][1]);
        __half2 h1 = __floats2half2_rn(acc[i][2], acc[i][3]);
        __half2* dst = (__half2*)(g_enc_projh + (size_t)(bm + ty * 4 + i) * H + bn + tx * 4);
        dst[0] = h0; dst[1] = h1;
    }
}

// ---------------- scores(+exp) + scatter(t-1) + ext(t-1) + ctx zero --------
__global__ __launch_bounds__(256) void k_scores(const float* __restrict__ w_cov,
                                                const float* __restrict__ v_att,
                                                const int* __restrict__ slen,
                                                const int* __restrict__ oov,
                                                float* __restrict__ out, int t) {
    if (blockIdx.x >= NSB + NSCAT) {
        int eb = blockIdx.x - (NSB + NSCAT);
        long lin = (long)eb * 256 + threadIdx.x;
        if (lin < B * H) g_context[lin] = 0.0f;   // for attnctx(t)
        if (t == 0) return;
        // ext for step t-1 (atomicAdd onto zeroed buffer)
        int b = (int)(lin / V), v = (int)(lin % V);
        float val = g_pgen[b] * g_expl[lin] * __fdividef(1.0f, g_rowsum[b]);
        atomicAdd(out + OD + ((long)b * TS + (t - 1)) * VEXT + v, val);
        return;
    }
    if (blockIdx.x >= NSB) {
        if (t == 0) return;
        int lin = (blockIdx.x - NSB) * 256 + threadIdx.x;
        int b = lin / S, s = lin % S;
        float add = (1.0f - g_pgen[b]) * g_attn2[b * S + s];
        int idx = oov[b * S + s];
        atomicAdd(out + OD + ((long)b * TS + (t - 1)) * VEXT + idx, add);
        return;
    }
    // score region: warp per (b,s); block covers 8 consecutive s in one b
    __shared__ float se[8];
    int wid  = threadIdx.x >> 5;
    int gw   = blockIdx.x * 8 + wid;
    int lane = threadIdx.x & 31;
    int b = gw / S, s = gw % S;
    float cov = g_cov[b * S + s];
    const __half2* ep = (const __half2*)(g_enc_projh + (size_t)(b * S + s) * H);
    const float* dp = &g_decproj[b * H];
    float sum = 0.0f;
    #pragma unroll
    for (int i = 0; i < 8; i++) {
        int j = lane + i * 32;               // half2 index
        float2 e  = __half22float2(ep[j]);
        float2 d  = *(const float2*)(dp + 2 * j);
        float2 wc = *(const float2*)(w_cov + 2 * j);
        float2 va = *(const float2*)(v_att + 2 * j);
        sum += my_tanh(e.x + d.x + cov * wc.x) * va.x
             + my_tanh(e.y + d.y + cov * wc.y) * va.y;
    }
    #pragma unroll
    for (int o = 16; o; o >>= 1) sum += __shfl_xor_sync(0xFFFFFFFFu, sum, o);
    if (lane == 0) {
        float e = (s < slen[b]) ? my_exp(sum) : 0.0f;
        g_attn[b * S + s] = e;
        se[wid] = e;
    }
    __syncthreads();
    if (threadIdx.x == 0) {
        float tot = 0.0f;
        #pragma unroll
        for (int i = 0; i < 8; i++) tot += se[i];
        atomicAdd(&g_expsum[b], tot);
    }
}

// ---------------- light attn: scale + coverage + context (grid 8 x B) ------
__global__ __launch_bounds__(512) void k_attnctx(const float* __restrict__ enc) {
    int b = blockIdx.y, ch = blockIdx.x, t = threadIdx.x;
    int s0 = ch * 50;
    __shared__ float sa[50];
    __shared__ float scl[50];
    float inv = __fdividef(1.0f, g_expsum[b]);
    if (t < 50) {
        int si = b * S + s0 + t;
        float a = g_attn[si] * inv;
        float cov = g_cov[si];
        sa[t] = a;
        g_attn2[si] = a;
        g_cov[si]   = cov + a;
        scl[t] = fminf(a, cov);
    }
    __syncthreads();
    if (t == 0) {
        float cl = 0.0f;
        #pragma unroll
        for (int i = 0; i < 50; i++) cl += scl[i];
        atomicAdd(&g_covloss[b], cl);
    }
    float acc = 0.0f;
    const float* eb = enc + ((size_t)b * S + s0) * H + t;
    #pragma unroll 5
    for (int i = 0; i < 50; i++) acc += sa[i] * eb[(size_t)i * H];
    atomicAdd(&g_context[b * H + t], acc);
}

// ---------------- fused LSTM gates GEMM + cell pointwise -------------------
// block = 4 h x 4 gates x 32 b; 128 blocks
__global__ __launch_bounds__(128) void k_gatescell(const float* __restrict__ b_ih,
                                                   const float* __restrict__ b_hh,
                                                   const float* __restrict__ emb,
                                                   const int* __restrict__ tgt,
                                                   const float* __restrict__ w_ctx,
                                                   const float* __restrict__ w_decp,
                                                   const float* __restrict__ w_embp,
                                                   int t) {
    __shared__ alignas(16) float Ws[64][18];
    __shared__ alignas(16) float In[64][34];
    __shared__ float sg[16][33];
    int h0  = blockIdx.x * 4;
    int tid = threadIdx.x;
    int tj = tid >> 4, tb = tid & 15;
    const float* hsrc = g_hbuf + (t & 1) * (B * H);
    float acc[2][2] = {};
    for (int k0 = 0; k0 < NK; k0 += 64) {
        {   // stage fp16 weights: 16 j x 64 k
            int jl = tid >> 3, h8 = tid & 7;
            int jg = (jl >> 2) * 512 + h0 + (jl & 3);
            uint4 u = *(const uint4*)(g_Wg + (size_t)jg * NK + k0 + h8 * 8);
            const __half2* hp = (const __half2*)&u;
            #pragma unroll
            for (int q = 0; q < 4; q++) {
                float2 f = __half22float2(hp[q]);
                Ws[h8 * 8 + q * 2 + 0][jl] = f.x;
                Ws[h8 * 8 + q * 2 + 1][jl] = f.y;
            }
        }
        #pragma unroll
        for (int it = 0; it < 4; it++) {
            int lin = it * 128 + tid;
            int bb = lin >> 4, c4 = lin & 15;
            const float* src = (k0 < 256)
                ? emb + (size_t)tgt[bb * T + t] * E + k0
                : (k0 < 768 ? g_context + bb * H + (k0 - 256)
                            : hsrc      + bb * H + (k0 - 768));
            float4 v = *(const float4*)(src + c4 * 4);
            In[c4 * 4 + 0][bb] = v.x;
            In[c4 * 4 + 1][bb] = v.y;
            In[c4 * 4 + 2][bb] = v.z;
            In[c4 * 4 + 3][bb] = v.w;
        }
        __syncthreads();
        #pragma unroll
        for (int kk = 0; kk < 64; kk++) {
            float2 w  = *(const float2*)&Ws[kk][tj * 2];
            float2 in = *(const float2*)&In[kk][tb * 2];
            acc[0][0] += w.x * in.x; acc[0][1] += w.x * in.y;
            acc[1][0] += w.y * in.x; acc[1][1] += w.y * in.y;
        }
        __syncthreads();
    }
    #pragma unroll
    for (int ii = 0; ii < 2; ii++) {
        int jl = tj * 2 + ii;
        int jg = (jl >> 2) * 512 + h0 + (jl & 3);
        float bias = b_ih[jg] + b_hh[jg];
        #pragma unroll
        for (int jb = 0; jb < 2; jb++)
            sg[jl][tb * 2 + jb] = acc[ii][jb] + bias;
    }
    __syncthreads();
    // cell pointwise: thread = (i,b)
    int i = tid >> 5, b = tid & 31, h = h0 + i;
    float gi = sg[i][b], gf = sg[4 + i][b], gg = sg[8 + i][b], go = sg[12 + i][b];
    float c_new = my_sigm(gf) * g_c[b * H + h] + my_sigm(gi) * my_tanh(gg);
    float h_new = my_sigm(go) * my_tanh(c_new);
    g_c[b * H + h] = c_new;
    g_hbuf[((t + 1) & 1) * (B * H) + b * H + h] = h_new;
    float ctx = g_context[b * H + h];
    g_hch[b * KV + h]     = __float2half_rn(h_new);
    g_hch[b * KV + H + h] = __float2half_rn(ctx);
    float p = ctx * w_ctx[h] + h_new * w_decp[h];
    if (h < E) p += emb[(size_t)tgt[b * T + t] * E + h] * w_embp[h];
    atomicAdd(&g_pgenacc[b], p);
    if (blockIdx.x == 0 && tid < 32) { g_rowsum[tid] = 0.0f; g_expsum[tid] = 0.0f; }
}

// ---------------- vocab logits mma + decproj + pgen finalize ---------------
__global__ __launch_bounds__(128) void k_logits(const float* __restrict__ bo,
                                                const float* __restrict__ b_att,
                                                const float* __restrict__ b_pgen,
                                                int t) {
    __shared__ alignas(16) unsigned char sm[16896];
    int tid = threadIdx.x;

    if (blockIdx.x >= VB) {
        const float* hsrc = g_hbuf + ((t + 1) & 1) * (B * H);
        if (blockIdx.x == VB && tid < 32) {
            g_pgen[tid] = my_sigm(g_pgenacc[tid] + b_pgen[0]);
            g_pgenacc[tid] = 0.0f;
        }
        float (*Wd)[18] = (float(*)[18])sm;
        float (*In)[34] = (float(*)[34])(sm + 4608);
        int j0 = (blockIdx.x - VB) * 16;
        int tj = tid >> 4, tb = tid & 15;
        float acc[2][2] = {};
        for (int k0 = 0; k0 < H; k0 += 64) {
            #pragma unroll
            for (int it = 0; it < 2; it++) {
                int lin = it * 128 + tid;
                int j = lin >> 4, c4 = lin & 15;
                float4 w = *(const float4*)&g_Wdt[(size_t)(j0 + j) * H + k0 + c4 * 4];
                Wd[c4 * 4 + 0][j] = w.x;
                Wd[c4 * 4 + 1][j] = w.y;
                Wd[c4 * 4 + 2][j] = w.z;
                Wd[c4 * 4 + 3][j] = w.w;
            }
            #pragma unroll
            for (int it = 0; it < 4; it++) {
                int lin = it * 128 + tid;
                int bb = lin >> 4, c4 = lin & 15;
                float4 v = *(const float4*)&hsrc[bb * H + k0 + c4 * 4];
                In[c4 * 4 + 0][bb] = v.x;
                In[c4 * 4 + 1][bb] = v.y;
                In[c4 * 4 + 2][bb] = v.z;
                In[c4 * 4 + 3][bb] = v.w;
            }
            __syncthreads();
            #pragma unroll
            for (int kk = 0; kk < 64; kk++) {
                float2 w  = *(const float2*)&Wd[kk][tj * 2];
                float2 in = *(const float2*)&In[kk][tb * 2];
                acc[0][0] += w.x * in.x; acc[0][1] += w.x * in.y;
                acc[1][0] += w.y * in.x; acc[1][1] += w.y * in.y;
            }
            __syncthreads();
        }
        #pragma unroll
        for (int ii = 0; ii < 2; ii++) {
            int jg = j0 + tj * 2 + ii;
            float ba = b_att[jg];
            #pragma unroll
            for (int jb = 0; jb < 2; jb++) {
                int b = tb * 2 + jb;
                g_decproj[b * H + jg] = acc[ii][jb] + ba;
            }
        }
        return;
    }

    // ---- vocab mma branch ----
    int w = tid >> 5, l = tid & 31;
    int g = l >> 2, tg = l & 3;
    int vt = blockIdx.x * 16 + w * 4;   // v8 base for this warp
    int vw = blockIdx.x * 128 + w * 32;
    float acc[2][4][4] = {};
    size_t bidx[4];
    #pragma unroll
    for (int n = 0; n < 4; n++) bidx[n] = ((size_t)(vt + n) * 64) * 32 + l;

    unsigned bcur[4][2], bnxt[4][2];
    #pragma unroll
    for (int n = 0; n < 4; n++) {
        uint2 u = g_Wp[bidx[n]];
        bcur[n][0] = u.x; bcur[n][1] = u.y;
    }
    for (int kc = 0; kc < KV; kc += 256) {
        #pragma unroll
        for (int i = 0; i < 8; i++) {
            int u = i * 128 + tid;
            int r = u >> 5, cu = u & 31;
            uint4 v4 = *(const uint4*)(g_hch + r * KV + kc + cu * 8);
            *(uint4*)(sm + r * 528 + cu * 16) = v4;
        }
        __syncthreads();
        int kg0 = kc >> 4;
        #pragma unroll
        for (int ks = 0; ks < 16; ks++) {
            int kgn = kg0 + ks + 1;
            if (kgn < 64) {
                #pragma unroll
                for (int n = 0; n < 4; n++) {
                    uint2 u = g_Wp[bidx[n] + (size_t)kgn * 32];
                    bnxt[n][0] = u.x; bnxt[n][1] = u.y;
                }
            }
            unsigned a[2][4];
            #pragma unroll
            for (int m = 0; m < 2; m++) {
                const unsigned char* base = sm + (m * 16 + g) * 528 + ks * 32 + tg * 4;
                a[m][0] = *(const unsigned*)(base);
                a[m][1] = *(const unsigned*)(base + 8 * 528);
                a[m][2] = *(const unsigned*)(base + 16);
                a[m][3] = *(const unsigned*)(base + 8 * 528 + 16);
            }
            #pragma unroll
            for (int m = 0; m < 2; m++)
                #pragma unroll
                for (int n = 0; n < 4; n++)
                    mma16816(acc[m][n][0], acc[m][n][1], acc[m][n][2], acc[m][n][3],
                             a[m][0], a[m][1], a[m][2], a[m][3],
                             bcur[n][0], bcur[n][1]);
            #pragma unroll
            for (int n = 0; n < 4; n++) { bcur[n][0] = bnxt[n][0]; bcur[n][1] = bnxt[n][1]; }
        }
        __syncthreads();
    }
    // epilogue: bias, exp, store, rowsum
    float psum[4] = {};
    #pragma unroll
    for (int n = 0; n < 4; n++) {
        int vv = vw + n * 8 + tg * 2;
        bool ok = vv < V;
        int vc = ok ? vv : 0;
        float2 bo2 = *(const float2*)&bo[vc];
        #pragma unroll
        for (int m = 0; m < 2; m++) {
            float e0 = my_exp(acc[m][n][0] + bo2.x);
            float e1 = my_exp(acc[m][n][1] + bo2.y);
            float e2 = my_exp(acc[m][n][2] + bo2.x);
            float e3 = my_exp(acc[m][n][3] + bo2.y);
            if (ok) {
                int b1 = m * 16 + g, b2 = b1 + 8;
                *(float2*)&g_expl[(size_t)b1 * V + vv] = make_float2(e0, e1);
                *(float2*)&g_expl[(size_t)b2 * V + vv] = make_float2(e2, e3);
                psum[m * 2 + 0] += e0 + e1;
                psum[m * 2 + 1] += e2 + e3;
            }
        }
    }
    #pragma unroll
    for (int i = 0; i < 4; i++) {
        float s = psum[i];
        s += __shfl_xor_sync(0xFFFFFFFFu, s, 1);
        s += __shfl_xor_sync(0xFFFFFFFFu, s, 2);
        if (tg == 0) {
            int b = (i >> 1) * 16 + (i & 1) * 8 + g;
            atomicAdd(&g_rowsum[b], s);
        }
    }
}

// ---------------- final: h, c, cov loss + last-step ext + scatter ----------
__global__ __launch_bounds__(256) void k_final(float* __restrict__ out,
                                               const int* __restrict__ oov) {
    if (blockIdx.x == 0) {
        int t = threadIdx.x;
        const float* hb = g_hbuf + (TS & 1) * (B * H);
        for (int i = t; i < B * H; i += 256) {
            out[OH + i] = hb[i];
            out[OC + i] = g_c[i];
        }
        __shared__ float red[B];
        if (t < B) red[t] = g_covloss[t];
        __syncthreads();
        if (t == 0) {
            float s = 0.0f;
            #pragma unroll
            for (int i = 0; i < B; i++) s += red[i];
            out[OL] = s / ((float)B * (float)TS);
        }
        return;
    }
    if (blockIdx.x <= NSCAT) {
        int lin = (blockIdx.x - 1) * 256 + threadIdx.x;
        if (lin < B * S) {
            int b = lin / S, s = lin % S;
            float add = (1.0f - g_pgen[b]) * g_attn2[b * S + s];
            int idx = oov[b * S + s];
            atomicAdd(out + OD + ((long)b * TS + (TS - 1)) * VEXT + idx, add);
        }
        return;
    }
    long lin = (long)(blockIdx.x - 1 - NSCAT) * 256 + threadIdx.x;
    if (lin < (long)B * V) {
        int b = (int)(lin / V), v = (int)(lin % V);
        float val = g_pgen[b] * g_expl[lin] * __fdividef(1.0f, g_rowsum[b]);
        atomicAdd(out + OD + ((long)b * TS + (TS - 1)) * VEXT + v, val);
    }
}

// ---------------- launch ----------------
extern "C" void kernel_launch(void* const* d_in, const int* in_sizes, int n_in,
                              void* d_out, int out_size) {
    const int*   tgt    = (const int*)  d_in[0];
    const float* hidden = (const float*)d_in[1];
    const float* cell   = (const float*)d_in[2];
    const float* enc    = (const float*)d_in[3];
    const int*   slen   = (const int*)  d_in[4];
    const int*   oov    = (const int*)  d_in[5];
    const float* emb    = (const float*)d_in[6];
    const float* W_enc  = (const float*)d_in[7];
    const float* W_dec  = (const float*)d_in[8];
    const float* w_cov  = (const float*)d_in[9];
    const float* v_att  = (const float*)d_in[10];
    const float* b_att  = (const float*)d_in[11];
    const float* W_ih   = (const float*)d_in[12];
    const float* W_hh   = (const float*)d_in[13];
    const float* b_ih   = (const float*)d_in[14];
    const float* b_hh   = (const float*)d_in[15];
    const float* W_out  = (const float*)d_in[16];
    const float* b_out  = (const float*)d_in[17];
    const float* w_ctx  = (const float*)d_in[18];
    const float* w_decp = (const float*)d_in[19];
    const float* w_embp = (const float*)d_in[20];
    const float* b_pgen = (const float*)d_in[21];
    float* out = (float*)d_out;

    k_zero<<<(int)((OH / 4 + 255) / 256), 256>>>(out);
    k_wpack<<<(int)(((long)VP * KV / 2 + 255) / 256), 256>>>(W_out);
    k_gpack<<<(int)(((long)G4H * NK / 4 + 255) / 256), 256>>>(W_ih, W_hh);
    k_prep<<<dim3(16, 16), 256>>>(W_dec);
    k_setup<<<B, H>>>(hidden, cell, W_dec, b_att);
    k_encproj<<<dim3(H / 64, (B * S) / 64), 256>>>(enc, W_enc);

    for (int t = 0; t < TS; t++) {
        k_scores<<<GSC, 256>>>(w_cov, v_att, slen, oov, out, t);
        k_attnctx<<<dim3(8, B), 512>>>(enc);
        k_gatescell<<<128, 128>>>(b_ih, b_hh, emb, tgt, w_ctx, w_decp, w_embp, t);
        k_logits<<<VB + 32, 128>>>(b_out, b_att, b_pgen, t);
    }

    k_final<<<1 + NSCAT + NEXTV, 256>>>(out, oov);
}

// round 14
// speedup vs baseline: 1.3746x; 1.3746x over previous
#include <cuda_runtime.h>
#include <cuda_fp16.h>
#include <cuda_bf16.h>

// ---------------- problem constants ----------------
constexpr int B  = 32;
constexpr int S  = 400;
constexpr int T  = 64;
constexpr int TS = T - 1;      // 63 steps
constexpr int H  = 512;
constexpr int E  = 256;
constexpr int V  = 50000;
constexpr int NOOV = 50;
constexpr int VEXT = V + NOOV; // 50050
constexpr int G4H = 4 * H;     // 2048
constexpr int NK  = E + 2 * H; // 1280 combined LSTM K
constexpr int VB  = (V + 127) / 128;   // 391 vocab GEMM blocks
constexpr int VP  = VB * 128;          // 50048 padded vocab
constexpr int KV  = 2 * H;     // 1024

constexpr int NEXTB = (int)(((long)B * VEXT + 255) / 256);  // 6257

// output layout: all_dists [B][63][VEXT], h [B*H], c [B*H], cov_loss [1]
constexpr long OD = 0;
constexpr long OH = (long)B * TS * VEXT;
constexpr long OC = OH + (long)B * H;
constexpr long OL = OC + (long)B * H;

// ---------------- device scratch ----------------
__device__ uint2 g_Wp[(size_t)(VP / 8) * 64 * 32]; // 102.5 MB W_out fragments
__device__ __half g_enc_projh[B * S * H];          // 13.1 MB fp16 enc_proj
__device__ __half g_ench[B * S * H];               // 13.1 MB fp16 enc
__device__ __half g_Wg[G4H * NK];                  // 5.2 MB fp16 LSTM weights [j][k]
__device__ float g_expl[B * V];                    // exp(logits)
__device__ float g_attn[B * S];
__device__ float g_attn2[B * S];
__device__ float g_cov[B * S];
__device__ float g_covloss[B];
__device__ float g_decproj[B * H];                 // includes +b_att
__device__ float g_context[B * H];
__device__ float g_gates[B * G4H];
__device__ float g_h[B * H];
__device__ float g_c[B * H];
__device__ __half g_hch[B * KV];                   // [h_new | ctx] fp16
__device__ float g_pgen[B];
__device__ float g_rowsum[B];
__device__ float g_Wdt[H * H];                     // W_dec transposed

// ---------------- math helpers ----------------
__device__ __forceinline__ float my_exp(float x) { return __expf(x); }
__device__ __forceinline__ float my_tanh(float x) {
    float ax = fabsf(x);
    float t  = __expf(-2.0f * ax);
    float r  = __fdividef(1.0f - t, 1.0f + t);
    return copysignf(r, x);
}
__device__ __forceinline__ float my_sigm(float x) {
    return __fdividef(1.0f, 1.0f + __expf(-x));
}
__device__ __forceinline__ void mma16816(float& d0, float& d1, float& d2, float& d3,
                                         unsigned a0, unsigned a1, unsigned a2, unsigned a3,
                                         unsigned b0, unsigned b1) {
    asm("mma.sync.aligned.m16n8k16.row.col.f32.f16.f16.f32 "
        "{%0,%1,%2,%3}, {%4,%5,%6,%7}, {%8,%9}, {%0,%1,%2,%3};"
        : "+f"(d0), "+f"(d1), "+f"(d2), "+f"(d3)
        : "r"(a0), "r"(a1), "r"(a2), "r"(a3), "r"(b0), "r"(b1));
}

// ---------------- one-off: repack W_out into mma B-fragment layout --------
__global__ __launch_bounds__(256) void k_wpack(const float* __restrict__ W) {
    long wdx = (long)blockIdx.x * 256 + threadIdx.x;   // 4-byte word index
    if (wdx >= (long)VP * KV / 2) return;
    long chunk = wdx >> 6;
    int ww = (int)(wdx & 63);
    int lane = ww >> 1, word = ww & 1;
    int g = lane >> 2, tg = lane & 3;
    long v8 = chunk >> 6;
    int ks  = (int)(chunk & 63);
    long v = v8 * 8 + g;
    int k = ks * 16 + tg * 2 + word * 8;
    __half2 hv;
    if (v < V) {
        float2 f = *(const float2*)(W + v * KV + k);
        hv = __floats2half2_rn(f.x, f.y);
    } else {
        hv = __floats2half2_rn(0.f, 0.f);
    }
    ((unsigned*)g_Wp)[wdx] = *(unsigned*)&hv;
}

// ---------------- one-off: pack LSTM weights fp16 [j][1280] ----------------
__global__ __launch_bounds__(256) void k_gpack(const float* __restrict__ W_ih,
                                               const float* __restrict__ W_hh) {
    long idx = ((long)blockIdx.x * 256 + threadIdx.x) * 4;
    if (idx >= (long)G4H * NK) return;
    int j = (int)(idx / NK), k = (int)(idx % NK);
    const float* src = (k < 768) ? W_ih + (size_t)j * 768 + k
                                 : W_hh + (size_t)j * 512 + (k - 768);
    float4 f = *(const float4*)src;
    __half2* dst = (__half2*)(g_Wg + idx);
    dst[0] = __floats2half2_rn(f.x, f.y);
    dst[1] = __floats2half2_rn(f.z, f.w);
}

// ---------------- one-off: convert encoder outputs to fp16 ----------------
__global__ __launch_bounds__(256) void k_epack(const float* __restrict__ enc) {
    long idx = ((long)blockIdx.x * 256 + threadIdx.x) * 4;
    if (idx >= (long)B * S * H) return;
    float4 f = *(const float4*)(enc + idx);
    __half2* dst = (__half2*)(g_ench + idx);
    dst[0] = __floats2half2_rn(f.x, f.y);
    dst[1] = __floats2half2_rn(f.z, f.w);
}

// ---------------- one-off: transpose W_dec ----------------
__global__ __launch_bounds__(256) void k_prep(const float* __restrict__ W_dec) {
    __shared__ float tile[32][33];
    int x = blockIdx.x * 32, y = blockIdx.y * 32;
    int tx = threadIdx.x & 31, ty0 = threadIdx.x >> 5;
    for (int i = ty0; i < 32; i += 8)
        tile[i][tx] = W_dec[(y + i) * H + x + tx];
    __syncthreads();
    for (int i = ty0; i < 32; i += 8)
        g_Wdt[(x + i) * H + y + tx] = tile[tx][i];
}

// ---------------- setup: state init + initial decproj (+b_att) ------------
__global__ __launch_bounds__(512) void k_setup(const float* __restrict__ hidden,
                                               const float* __restrict__ cell,
                                               const float* __restrict__ W_dec,
                                               const float* __restrict__ b_att) {
    int b = blockIdx.x, h = threadIdx.x;
    __shared__ float sh[H];
    float hv = hidden[b * H + h];
    g_h[b * H + h] = hv;
    g_c[b * H + h] = cell[b * H + h];
    g_context[b * H + h] = 0.0f;
    sh[h] = hv;
    if (h < S) g_cov[b * S + h] = 0.0f;
    if (h == 0) g_covloss[b] = 0.0f;
    __syncthreads();
    float acc = 0.0f;
    #pragma unroll 8
    for (int k = 0; k < H; k++) acc += sh[k] * W_dec[k * H + h];
    g_decproj[b * H + h] = acc + b_att[h];
}

// ---------------- enc_proj = encoder_outputs @ W_enc (fp32, fp16 out) ------
__global__ __launch_bounds__(256) void k_encproj(const float* __restrict__ A,
                                                 const float* __restrict__ Bm) {
    __shared__ float As[16][68];
    __shared__ float Bs[16][68];
    const int N = H, K = H;
    int bm = blockIdx.y * 64, bn = blockIdx.x * 64;
    int tx = threadIdx.x & 15, ty = threadIdx.x >> 4;
    float acc[4][4] = {};
    for (int k0 = 0; k0 < K; k0 += 16) {
        #pragma unroll
        for (int i = 0; i < 4; i++) {
            int lin = threadIdx.x + i * 256;
            int r = lin >> 4, c = lin & 15;
            As[c][r] = A[(size_t)(bm + r) * K + k0 + c];
            int r2 = lin >> 6, c2 = lin & 63;
            Bs[r2][c2] = Bm[(size_t)(k0 + r2) * N + bn + c2];
        }
        __syncthreads();
        #pragma unroll
        for (int kk = 0; kk < 16; kk++) {
            float4 a4 = *(const float4*)&As[kk][ty * 4];
            float4 b4 = *(const float4*)&Bs[kk][tx * 4];
            float av[4] = {a4.x, a4.y, a4.z, a4.w};
            float bv[4] = {b4.x, b4.y, b4.z, b4.w};
            #pragma unroll
            for (int i = 0; i < 4; i++)
                #pragma unroll
                for (int j = 0; j < 4; j++) acc[i][j] += av[i] * bv[j];
        }
        __syncthreads();
    }
    #pragma unroll
    for (int i = 0; i < 4; i++) {
        __half2 h0 = __floats2half2_rn(acc[i][0], acc[i][1]);
        __half2 h1 = __floats2half2_rn(acc[i][2], acc[i][3]);
        __half2* dst = (__half2*)(g_enc_projh + (size_t)(bm + ty * 4 + i) * H + bn + tx * 4);
        dst[0] = h0; dst[1] = h1;
    }
}

// ---------------- scores + scatter(t-1) ----------------
__global__ __launch_bounds__(256) void k_scores(const float* __restrict__ w_cov,
                                                const float* __restrict__ v_att,
                                                const int* __restrict__ slen,
                                                const int* __restrict__ oov,
                                                float* __restrict__ out, int t) {
    if (blockIdx.x >= 1600) {
        if (t == 0) return;
        int lin = (blockIdx.x - 1600) * 256 + threadIdx.x;
        int b = lin / S, s = lin % S;
        float add = (1.0f - g_pgen[b]) * g_attn2[b * S + s];
        int idx = oov[b * S + s];
        atomicAdd(out + OD + ((long)b * TS + (t - 1)) * VEXT + idx, add);
        return;
    }
    int gw   = (blockIdx.x * blockDim.x + threadIdx.x) >> 5;
    int lane = threadIdx.x & 31;
    int b = gw / S, s = gw % S;
    float cov = g_cov[b * S + s];
    const __half2* ep = (const __half2*)(g_enc_projh + (size_t)(b * S + s) * H);
    const float* dp = &g_decproj[b * H];
    float sum = 0.0f;
    #pragma unroll
    for (int i = 0; i < 8; i++) {
        int j = lane + i * 32;               // half2 index
        float2 e  = __half22float2(ep[j]);
        float2 d  = *(const float2*)(dp + 2 * j);
        float2 wc = *(const float2*)(w_cov + 2 * j);
        float2 va = *(const float2*)(v_att + 2 * j);
        sum += my_tanh(e.x + d.x + cov * wc.x) * va.x
             + my_tanh(e.y + d.y + cov * wc.y) * va.y;
    }
    #pragma unroll
    for (int o = 16; o; o >>= 1) sum += __shfl_xor_sync(0xFFFFFFFFu, sum, o);
    if (lane == 0) g_attn[b * S + s] = (s < slen[b]) ? sum : -1e9f;
}

// ---------------- fused softmax + coverage + context (grid 8 x B) ----------
__global__ __launch_bounds__(512) void k_attnctx() {
    int b = blockIdx.y, ch = blockIdx.x, t = threadIdx.x;
    __shared__ float red[512];
    __shared__ float sa[50];
    float sc = (t < S) ? g_attn[b * S + t] : -3.0e38f;
    red[t] = sc; __syncthreads();
    #pragma unroll
    for (int o = 256; o > 0; o >>= 1) { if (t < o) red[t] = fmaxf(red[t], red[t + o]); __syncthreads(); }
    float mx = red[0]; __syncthreads();
    float e = (t < S) ? my_exp(sc - mx) : 0.0f;
    red[t] = e; __syncthreads();
    #pragma unroll
    for (int o = 256; o > 0; o >>= 1) { if (t < o) red[t] += red[t + o]; __syncthreads(); }
    float inv = __fdividef(1.0f, red[0]); __syncthreads();
    float a = e * inv;
    int s0 = ch * 50;
    float cl = 0.0f;
    if (t >= s0 && t < s0 + 50) {
        float cov = g_cov[b * S + t];
        sa[t - s0] = a;
        g_attn2[b * S + t] = a;
        g_cov[b * S + t]   = cov + a;
        cl = fminf(a, cov);
    }
    red[t] = cl; __syncthreads();
    #pragma unroll
    for (int o = 256; o > 0; o >>= 1) { if (t < o) red[t] += red[t + o]; __syncthreads(); }
    if (t == 0) atomicAdd(&g_covloss[b], red[0]);
    float acc = 0.0f;
    const __half* eb = g_ench + ((size_t)b * S + s0) * H + t;
    #pragma unroll 5
    for (int i = 0; i < 50; i++) acc += sa[i] * __half2float(eb[(size_t)i * H]);
    atomicAdd(&g_context[b * H + t], acc);
}

// ---------------- LSTM gates: tiled GEMM (fp16 weights), 16j x 32b ----------
__global__ __launch_bounds__(128) void k_gates(const float* __restrict__ b_ih,
                                               const float* __restrict__ b_hh,
                                               const float* __restrict__ emb,
                                               const int* __restrict__ tgt, int t) {
    __shared__ alignas(16) float Ws[64][18];
    __shared__ alignas(16) float In[64][34];
    int j0  = blockIdx.x * 16;
    int tid = threadIdx.x;
    int tj = tid >> 4, tb = tid & 15;
    float acc[2][2] = {};
    for (int k0 = 0; k0 < NK; k0 += 64) {
        {
            int j = tid >> 3, h8 = tid & 7;
            uint4 u = *(const uint4*)(g_Wg + (size_t)(j0 + j) * NK + k0 + h8 * 8);
            const __half2* hp = (const __half2*)&u;
            #pragma unroll
            for (int q = 0; q < 4; q++) {
                float2 f = __half22float2(hp[q]);
                Ws[h8 * 8 + q * 2 + 0][j] = f.x;
                Ws[h8 * 8 + q * 2 + 1][j] = f.y;
            }
        }
        #pragma unroll
        for (int it = 0; it < 4; it++) {
            int lin = it * 128 + tid;
            int bb = lin >> 4, c4 = lin & 15;
            const float* src = (k0 < 256)
                ? emb + (size_t)tgt[bb * T + t] * E + k0
                : (k0 < 768 ? g_context + bb * H + (k0 - 256)
                            : g_h      + bb * H + (k0 - 768));
            float4 v = *(const float4*)(src + c4 * 4);
            In[c4 * 4 + 0][bb] = v.x;
            In[c4 * 4 + 1][bb] = v.y;
            In[c4 * 4 + 2][bb] = v.z;
            In[c4 * 4 + 3][bb] = v.w;
        }
        __syncthreads();
        #pragma unroll
        for (int kk = 0; kk < 64; kk++) {
            float2 w  = *(const float2*)&Ws[kk][tj * 2];
            float2 in = *(const float2*)&In[kk][tb * 2];
            acc[0][0] += w.x * in.x; acc[0][1] += w.x * in.y;
            acc[1][0] += w.y * in.x; acc[1][1] += w.y * in.y;
        }
        __syncthreads();
    }
    #pragma unroll
    for (int i = 0; i < 2; i++) {
        int jg = j0 + tj * 2 + i;
        float bias = b_ih[jg] + b_hh[jg];
        #pragma unroll
        for (int jb = 0; jb < 2; jb++) {
            int b = tb * 2 + jb;
            g_gates[b * G4H + jg] = acc[i][jb] + bias;
        }
    }
}

// ---------------- cell pointwise + pgen + hc(fp16) ----------------
__global__ __launch_bounds__(512) void k_cell(const float* __restrict__ w_ctx,
                                              const float* __restrict__ w_decp,
                                              const float* __restrict__ w_embp,
                                              const float* __restrict__ b_pgen,
                                              const float* __restrict__ emb,
                                              const int* __restrict__ tgt, int t) {
    int b = blockIdx.x, h = threadIdx.x;
    const float* gb = g_gates + b * G4H;
    float gi = gb[h], gf = gb[H + h], gg = gb[2 * H + h], go = gb[3 * H + h];
    float c_new = my_sigm(gf) * g_c[b * H + h] + my_sigm(gi) * my_tanh(gg);
    float h_new = my_sigm(go) * my_tanh(c_new);
    g_c[b * H + h] = c_new;
    g_h[b * H + h] = h_new;
    float ctx = g_context[b * H + h];
    g_hch[b * KV + h]     = __float2half_rn(h_new);
    g_hch[b * KV + H + h] = __float2half_rn(ctx);
    __shared__ float red[512];
    float p = ctx * w_ctx[h] + h_new * w_decp[h];
    if (h < E) p += emb[(size_t)tgt[b * T + t] * E + h] * w_embp[h];
    red[h] = p; __syncthreads();
    #pragma unroll
    for (int o = 256; o > 0; o >>= 1) { if (h < o) red[h] += red[h + o]; __syncthreads(); }
    if (h == 0) {
        g_pgen[b]   = my_sigm(red[0] + b_pgen[0]);
        g_rowsum[b] = 0.0f;
    }
}

// ---------------- vocab logits: fp16 mma, deep W pipeline + resident A -----
// blocks [0,VB): 128v x 32b, warp tile 32v x 32b; blocks [VB,VB+32): decproj
__global__ __launch_bounds__(128) void k_logits(const float* __restrict__ bo,
                                                const float* __restrict__ b_att) {
    __shared__ alignas(16) unsigned char sm[33280];
    int tid = threadIdx.x;

    if (blockIdx.x >= VB) {
        float (*Wd)[18] = (float(*)[18])sm;
        float (*In)[34] = (float(*)[34])(sm + 4608);
        int j0 = (blockIdx.x - VB) * 16;
        int tj = tid >> 4, tb = tid & 15;
        float acc[2][2] = {};
        for (int k0 = 0; k0 < H; k0 += 64) {
            #pragma unroll
            for (int it = 0; it < 2; it++) {
                int lin = it * 128 + tid;
                int j = lin >> 4, c4 = lin & 15;
                float4 w = *(const float4*)&g_Wdt[(size_t)(j0 + j) * H + k0 + c4 * 4];
                Wd[c4 * 4 + 0][j] = w.x;
                Wd[c4 * 4 + 1][j] = w.y;
                Wd[c4 * 4 + 2][j] = w.z;
                Wd[c4 * 4 + 3][j] = w.w;
            }
            #pragma unroll
            for (int it = 0; it < 4; it++) {
                int lin = it * 128 + tid;
                int bb = lin >> 4, c4 = lin & 15;
                float4 v = *(const float4*)&g_h[bb * H + k0 + c4 * 4];
                In[c4 * 4 + 0][bb] = v.x;
                In[c4 * 4 + 1][bb] = v.y;
                In[c4 * 4 + 2][bb] = v.z;
                In[c4 * 4 + 3][bb] = v.w;
            }
            __syncthreads();
            #pragma unroll
            for (int kk = 0; kk < 64; kk++) {
                float2 w  = *(const float2*)&Wd[kk][tj * 2];
                float2 in = *(const float2*)&In[kk][tb * 2];
                acc[0][0] += w.x * in.x; acc[0][1] += w.x * in.y;
                acc[1][0] += w.y * in.x; acc[1][1] += w.y * in.y;
            }
            __syncthreads();
        }
        #pragma unroll
        for (int i = 0; i < 2; i++) {
            int jg = j0 + tj * 2 + i;
            float ba = b_att[jg];
            #pragma unroll
            for (int jb = 0; jb < 2; jb++) {
                int b = tb * 2 + jb;
                g_decproj[b * H + jg] = acc[i][jb] + ba;
            }
        }
        return;
    }

    // ---- vocab mma branch ----
    int w = tid >> 5, l = tid & 31;
    int g = l >> 2, tg = l & 3;
    int vt = blockIdx.x * 16 + w * 4;   // v8 base for this warp
    int vw = blockIdx.x * 128 + w * 32;
    float acc[2][4][4] = {};
    const uint2* wp[4];
    #pragma unroll
    for (int n = 0; n < 4; n++)
        wp[n] = g_Wp + ((size_t)(vt + n) * 64) * 32 + l;
    // depth-4 register pipeline of W fragments
    uint2 breg[4][4];
    #pragma unroll
    for (int d = 0; d < 4; d++)
        #pragma unroll
        for (int n = 0; n < 4; n++)
            breg[d][n] = wp[n][(size_t)d * 32];
    #pragma unroll
    for (int c = 0; c < 2; c++) {
        // stage A chunk: 32 rows x 512 halves, row stride 1040 B (conflict-free)
        #pragma unroll
        for (int it = 0; it < 16; it++) {
            int u = it * 128 + tid;
            int r = u >> 6, cu = u & 63;
            uint4 v4 = *(const uint4*)(g_hch + r * KV + c * 512 + cu * 8);
            *(uint4*)(sm + r * 1040 + cu * 16) = v4;
        }
        __syncthreads();
        #pragma unroll
        for (int ks2 = 0; ks2 < 32; ks2++) {
            int ks = c * 32 + ks2;
            int d = ks & 3;
            unsigned a[2][4];
            #pragma unroll
            for (int m = 0; m < 2; m++) {
                const unsigned char* base = sm + (m * 16 + g) * 1040 + ks2 * 32 + tg * 4;
                a[m][0] = *(const unsigned*)(base);
                a[m][1] = *(const unsigned*)(base + 8 * 1040);
                a[m][2] = *(const unsigned*)(base + 16);
                a[m][3] = *(const unsigned*)(base + 8 * 1040 + 16);
            }
            uint2 bc[4];
            #pragma unroll
            for (int n = 0; n < 4; n++) bc[n] = breg[d][n];
            if (ks + 4 < 64) {
                #pragma unroll
                for (int n = 0; n < 4; n++)
                    breg[d][n] = wp[n][(size_t)(ks + 4) * 32];
            }
            #pragma unroll
            for (int m = 0; m < 2; m++)
                #pragma unroll
                for (int n = 0; n < 4; n++)
                    mma16816(acc[m][n][0], acc[m][n][1], acc[m][n][2], acc[m][n][3],
                             a[m][0], a[m][1], a[m][2], a[m][3],
                             bc[n].x, bc[n].y);
        }
        __syncthreads();
    }
    // epilogue: bias, exp, store, rowsum
    float psum[4] = {};
    #pragma unroll
    for (int n = 0; n < 4; n++) {
        int vv = vw + n * 8 + tg * 2;
        bool ok = vv < V;
        int vc = ok ? vv : 0;
        float2 bo2 = *(const float2*)&bo[vc];
        #pragma unroll
        for (int m = 0; m < 2; m++) {
            float e0 = my_exp(acc[m][n][0] + bo2.x);
            float e1 = my_exp(acc[m][n][1] + bo2.y);
            float e2 = my_exp(acc[m][n][2] + bo2.x);
            float e3 = my_exp(acc[m][n][3] + bo2.y);
            if (ok) {
                int b1 = m * 16 + g, b2 = b1 + 8;
                *(float2*)&g_expl[(size_t)b1 * V + vv] = make_float2(e0, e1);
                *(float2*)&g_expl[(size_t)b2 * V + vv] = make_float2(e2, e3);
                psum[m * 2 + 0] += e0 + e1;
                psum[m * 2 + 1] += e2 + e3;
            }
        }
    }
    #pragma unroll
    for (int i = 0; i < 4; i++) {
        float s = psum[i];
        s += __shfl_xor_sync(0xFFFFFFFFu, s, 1);
        s += __shfl_xor_sync(0xFFFFFFFFu, s, 2);
        if (tg == 0) {
            int b = (i >> 1) * 16 + (i & 1) * 8 + g;
            atomicAdd(&g_rowsum[b], s);
        }
    }
}

// ---------------- ext dist store (step t) + zero context for t+1 ----------
__global__ __launch_bounds__(256) void k_ext(float* __restrict__ out, int t) {
    long lin = (long)blockIdx.x * 256 + threadIdx.x;
    if (lin < B * H) g_context[lin] = 0.0f;
    if (lin >= (long)B * VEXT) return;
    int b = (int)(lin / VEXT), v = (int)(lin % VEXT);
    float val = 0.0f;
    if (v < V)
        val = g_pgen[b] * g_expl[(size_t)b * V + v] * __fdividef(1.0f, g_rowsum[b]);
    out[OD + ((long)b * TS + t) * VEXT + v] = val;
}

// ---------------- final: h, c, cov loss + last-step scatter ----------------
__global__ __launch_bounds__(256) void k_final(float* __restrict__ out,
                                               const int* __restrict__ oov) {
    if (blockIdx.x == 0) {
        int t = threadIdx.x;
        for (int i = t; i < B * H; i += 256) {
            out[OH + i] = g_h[i];
            out[OC + i] = g_c[i];
        }
        __shared__ float red[B];
        if (t < B) red[t] = g_covloss[t];
        __syncthreads();
        if (t == 0) {
            float s = 0.0f;
            #pragma unroll
            for (int i = 0; i < B; i++) s += red[i];
            out[OL] = s / ((float)B * (float)TS);
        }
        return;
    }
    int lin = (blockIdx.x - 1) * 256 + threadIdx.x;
    if (lin < B * S) {
        int b = lin / S, s = lin % S;
        float add = (1.0f - g_pgen[b]) * g_attn2[b * S + s];
        int idx = oov[b * S + s];
        atomicAdd(out + OD + ((long)b * TS + (TS - 1)) * VEXT + idx, add);
    }
}

// ---------------- launch ----------------
extern "C" void kernel_launch(void* const* d_in, const int* in_sizes, int n_in,
                              void* d_out, int out_size) {
    const int*   tgt    = (const int*)  d_in[0];
    const float* hidden = (const float*)d_in[1];
    const float* cell   = (const float*)d_in[2];
    const float* enc    = (const float*)d_in[3];
    const int*   slen   = (const int*)  d_in[4];
    const int*   oov    = (const int*)  d_in[5];
    const float* emb    = (const float*)d_in[6];
    const float* W_enc  = (const float*)d_in[7];
    const float* W_dec  = (const float*)d_in[8];
    const float* w_cov  = (const float*)d_in[9];
    const float* v_att  = (const float*)d_in[10];
    const float* b_att  = (const float*)d_in[11];
    const float* W_ih   = (const float*)d_in[12];
    const float* W_hh   = (const float*)d_in[13];
    const float* b_ih   = (const float*)d_in[14];
    const float* b_hh   = (const float*)d_in[15];
    const float* W_out  = (const float*)d_in[16];
    const float* b_out  = (const float*)d_in[17];
    const float* w_ctx  = (const float*)d_in[18];
    const float* w_decp = (const float*)d_in[19];
    const float* w_embp = (const float*)d_in[20];
    const float* b_pgen = (const float*)d_in[21];
    float* out = (float*)d_out;

    k_wpack<<<(int)(((long)VP * KV / 2 + 255) / 256), 256>>>(W_out);
    k_gpack<<<(int)(((long)G4H * NK / 4 + 255) / 256), 256>>>(W_ih, W_hh);
    k_epack<<<(int)(((long)B * S * H / 4 + 255) / 256), 256>>>(enc);
    k_prep<<<dim3(16, 16), 256>>>(W_dec);
    k_setup<<<B, H>>>(hidden, cell, W_dec, b_att);
    k_encproj<<<dim3(H / 64, (B * S) / 64), 256>>>(enc, W_enc);

    for (int t = 0; t < TS; t++) {
        k_scores<<<1650, 256>>>(w_cov, v_att, slen, oov, out, t);
        k_attnctx<<<dim3(8, B), 512>>>();
        k_gates<<<G4H / 16, 128>>>(b_ih, b_hh, emb, tgt, t);
        k_cell<<<B, 512>>>(w_ctx, w_decp, w_embp, b_pgen, emb, tgt, t);
        k_logits<<<VB + 32, 128>>>(b_out, b_att);
        k_ext<<<NEXTB, 256>>>(out, t);
    }

    k_final<<<51, 256>>>(out, oov);
}